// round 2
// baseline (speedup 1.0000x reference)
#include <cuda_runtime.h>

#define N_NODES  100000
#define HIDDEN   128
#define NUM_PATH 8
#define PATH_LEN 4
#define NUM_E    2

#define NPB      64      // nodes per block
#define THREADS  256
#define KT       32      // GEMM k-tile
#define WP       129     // Wsm pitch (conflict-free)

#define FOUT_W   (2*HIDDEN)   // 256
#define SMEM_BYTES (NPB*FOUT_W*4 + KT*WP*4)   // 65536 + 16512 = 82048

__global__ __launch_bounds__(THREADS, 2)
void impeller_fused_kernel(const float4* __restrict__ feats,
                           const int* __restrict__ paths,
                           const int* __restrict__ ptypes,
                           const float* __restrict__ pweights,
                           const float* __restrict__ W,
                           float* __restrict__ out)
{
    extern __shared__ float smem[];
    float* Fsm = smem;                       // [NPB][FOUT_W]
    float* Wsm = smem + NPB * FOUT_W;        // [KT][WP]

    const int tid  = threadIdx.x;
    const int lane = tid & 31;
    const int wid  = tid >> 5;
    const int nblk = blockIdx.x * NPB;

    // ---- per-lane (path, hop) coefficient: lane k -> p = k/4, l = k%4 ----
    const int p = lane >> 2;
    const int l = lane & 3;
    const int t = ptypes[p];
    int cnt0 = 0, cnt1 = 0;
    #pragma unroll
    for (int q = 0; q < NUM_PATH; q++) {
        int tq = ptypes[q];
        cnt0 += (tq == 0);
        cnt1 += (tq == 1);
    }
    const float cw = pweights[t * PATH_LEN + l] /
                     (float)((t == 0) ? cnt0 : cnt1);
    const float c0 = (t == 0) ? cw : 0.f;
    const float c1 = (t == 1) ? cw : 0.f;

    // ================= Phase 1: gather + weighted accumulate =================
    // Each warp processes 8 nodes; per node, lane k owns index of pair k.
    #pragma unroll
    for (int it = 0; it < NPB / 8; it++) {
        const int n_local = wid * 8 + it;
        const int n = nblk + n_local;
        const bool valid = (n < N_NODES);

        int idx = 0;
        if (valid) {
            idx = paths[(size_t)p * (N_NODES * PATH_LEN)
                        + (size_t)n * PATH_LEN + l];
        }

        float4 a0 = make_float4(0.f, 0.f, 0.f, 0.f);
        float4 a1 = make_float4(0.f, 0.f, 0.f, 0.f);

        if (valid) {
            #pragma unroll
            for (int k = 0; k < 32; k++) {
                const int   id = __shfl_sync(0xffffffffu, idx, k);
                const float w0 = __shfl_sync(0xffffffffu, c0, k);
                const float w1 = __shfl_sync(0xffffffffu, c1, k);
                const float4 v = __ldg(&feats[(size_t)id * (HIDDEN / 4) + lane]);
                a0.x += w0 * v.x; a0.y += w0 * v.y;
                a0.z += w0 * v.z; a0.w += w0 * v.w;
                a1.x += w1 * v.x; a1.y += w1 * v.y;
                a1.z += w1 * v.z; a1.w += w1 * v.w;
            }
        }
        // fout row: [type0 cols 0..127 | type1 cols 128..255]
        *(float4*)&Fsm[n_local * FOUT_W + lane * 4]          = a0;
        *(float4*)&Fsm[n_local * FOUT_W + HIDDEN + lane * 4] = a1;
    }
    __syncthreads();

    // ================= Phase 2: OUT(64x128) = FOUT(64x256) @ W^T =================
    // thread (tx,ty): rows ty*8..ty*8+7, cols tx + 32*c  (c = 0..3)
    const int tx = tid & 31;
    const int ty = tid >> 5;

    float acc[8][4];
    #pragma unroll
    for (int r = 0; r < 8; r++)
        #pragma unroll
        for (int cc = 0; cc < 4; cc++)
            acc[r][cc] = 0.f;

    for (int k0 = 0; k0 < FOUT_W; k0 += KT) {
        // stage W tile: Wsm[kk][j] = W[j][k0+kk]   (W is [128][256] row-major)
        #pragma unroll
        for (int i = 0; i < (KT * HIDDEN) / THREADS; i++) {   // 16
            const int e  = tid + i * THREADS;
            const int j  = e >> 5;
            const int kk = e & 31;
            Wsm[kk * WP + j] = __ldg(&W[(size_t)j * FOUT_W + k0 + kk]);
        }
        __syncthreads();

        #pragma unroll
        for (int kk4 = 0; kk4 < KT; kk4 += 4) {
            float4 f[8];
            #pragma unroll
            for (int r = 0; r < 8; r++)
                f[r] = *(const float4*)&Fsm[(ty * 8 + r) * FOUT_W + k0 + kk4];

            #pragma unroll
            for (int kk = 0; kk < 4; kk++) {
                float wv[4];
                #pragma unroll
                for (int cc = 0; cc < 4; cc++)
                    wv[cc] = Wsm[(kk4 + kk) * WP + tx + 32 * cc];
                #pragma unroll
                for (int r = 0; r < 8; r++) {
                    const float fv = (kk == 0) ? f[r].x :
                                     (kk == 1) ? f[r].y :
                                     (kk == 2) ? f[r].z : f[r].w;
                    #pragma unroll
                    for (int cc = 0; cc < 4; cc++)
                        acc[r][cc] += fv * wv[cc];
                }
            }
        }
        __syncthreads();
    }

    // ================= Epilogue: ReLU + store =================
    #pragma unroll
    for (int r = 0; r < 8; r++) {
        const int n = nblk + ty * 8 + r;
        if (n < N_NODES) {
            #pragma unroll
            for (int cc = 0; cc < 4; cc++) {
                const float v = acc[r][cc];
                out[(size_t)n * HIDDEN + tx + 32 * cc] = (v > 0.f) ? v : 0.f;
            }
        }
    }
}

extern "C" void kernel_launch(void* const* d_in, const int* in_sizes, int n_in,
                              void* d_out, int out_size)
{
    const float4* feats    = (const float4*)d_in[0];
    const int*    paths    = (const int*)d_in[1];
    const int*    ptypes   = (const int*)d_in[2];
    const float*  pweights = (const float*)d_in[3];
    const float*  W        = (const float*)d_in[4];
    float*        out      = (float*)d_out;

    cudaFuncSetAttribute(impeller_fused_kernel,
                         cudaFuncAttributeMaxDynamicSharedMemorySize,
                         SMEM_BYTES);

    const int blocks = (N_NODES + NPB - 1) / NPB;
    impeller_fused_kernel<<<blocks, THREADS, SMEM_BYTES>>>(
        feats, paths, ptypes, pweights, W, out);
}

// round 4
// speedup vs baseline: 1.4858x; 1.4858x over previous
#include <cuda_runtime.h>
#include <cuda_bf16.h>
#include <cstdint>

#define N_NODES  100000
#define HIDDEN   128
#define NUM_PATH 8
#define PATH_LEN 4

#define NPB      128       // nodes per CTA (= GEMM M)
#define THREADS  512       // 16 warps
#define FOUT_W   256       // K of GEMM
#define KCHUNK   64        // W staging chunk along K

#define AP   264           // A pitch (bf16 elems), 528B = 16*33
#define WPIT 72            // W chunk pitch (bf16 elems), 144B = 16*9

// smem byte offsets
#define OFF_AHI   0
#define OFF_AMID  (128*AP*2)                    // 67584
#define OFF_WHI   (2*128*AP*2)                  // 135168
#define OFF_WMID  (OFF_WHI + 128*WPIT*2)        // +18432
#define SMEM_TOTAL (OFF_WMID + 128*WPIT*2)      // 172032

__device__ __forceinline__ uint32_t smem_u32(const void* p) {
    uint32_t a;
    asm("{ .reg .u64 t; cvta.to.shared.u64 t, %1; cvt.u32.u64 %0, t; }"
        : "=r"(a) : "l"(p));
    return a;
}
__device__ __forceinline__ void ldm_x4(uint32_t& r0, uint32_t& r1,
                                       uint32_t& r2, uint32_t& r3, uint32_t addr) {
    asm volatile("ldmatrix.sync.aligned.m8n8.x4.shared.b16 {%0,%1,%2,%3}, [%4];"
                 : "=r"(r0), "=r"(r1), "=r"(r2), "=r"(r3) : "r"(addr));
}
__device__ __forceinline__ void ldm_x2(uint32_t& r0, uint32_t& r1, uint32_t addr) {
    asm volatile("ldmatrix.sync.aligned.m8n8.x2.shared.b16 {%0,%1}, [%2];"
                 : "=r"(r0), "=r"(r1) : "r"(addr));
}
__device__ __forceinline__ void hmma(float* c, const uint32_t* a, const uint32_t* b) {
    asm volatile(
        "mma.sync.aligned.m16n8k16.row.col.f32.bf16.bf16.f32 "
        "{%0,%1,%2,%3}, {%4,%5,%6,%7}, {%8,%9}, {%0,%1,%2,%3};"
        : "+f"(c[0]), "+f"(c[1]), "+f"(c[2]), "+f"(c[3])
        : "r"(a[0]), "r"(a[1]), "r"(a[2]), "r"(a[3]), "r"(b[0]), "r"(b[1]));
}

// fp32x4 -> (hi, mid) bf16x4; write 8B to each tile at byte offset `off`
__device__ __forceinline__ void store_split(char* smem, uint32_t hi_base,
                                            uint32_t mid_base, uint32_t off, float4 v) {
    __nv_bfloat16 h0 = __float2bfloat16(v.x);
    __nv_bfloat16 h1 = __float2bfloat16(v.y);
    __nv_bfloat16 h2 = __float2bfloat16(v.z);
    __nv_bfloat16 h3 = __float2bfloat16(v.w);
    __nv_bfloat16 m0 = __float2bfloat16(v.x - __bfloat162float(h0));
    __nv_bfloat16 m1 = __float2bfloat16(v.y - __bfloat162float(h1));
    __nv_bfloat16 m2 = __float2bfloat16(v.z - __bfloat162float(h2));
    __nv_bfloat16 m3 = __float2bfloat16(v.w - __bfloat162float(h3));
    __nv_bfloat162 H01 = __halves2bfloat162(h0, h1);
    __nv_bfloat162 H23 = __halves2bfloat162(h2, h3);
    __nv_bfloat162 M01 = __halves2bfloat162(m0, m1);
    __nv_bfloat162 M23 = __halves2bfloat162(m2, m3);
    *(uint2*)(smem + hi_base + off)  = make_uint2(*(uint32_t*)&H01, *(uint32_t*)&H23);
    *(uint2*)(smem + mid_base + off) = make_uint2(*(uint32_t*)&M01, *(uint32_t*)&M23);
}

__global__ __launch_bounds__(THREADS, 1)
void impeller_hmma_kernel(const float4* __restrict__ feats,
                          const int* __restrict__ paths,
                          const int* __restrict__ ptypes,
                          const float* __restrict__ pweights,
                          const float* __restrict__ W,
                          float* __restrict__ out)
{
    extern __shared__ char smem[];
    const uint32_t sb = smem_u32(smem);

    const int tid  = threadIdx.x;
    const int lane = tid & 31;
    const int wid  = tid >> 5;
    const int nblk = blockIdx.x * NPB;

    // ---- per-lane (path, hop) coefficient: lane k -> p=k/4, l=k%4 ----
    const int p = lane >> 2;
    const int l = lane & 3;
    const int t = ptypes[p];
    int cnt0 = 0, cnt1 = 0;
    #pragma unroll
    for (int q = 0; q < NUM_PATH; q++) {
        int tq = ptypes[q];
        cnt0 += (tq == 0);
        cnt1 += (tq == 1);
    }
    const float cw = pweights[t * PATH_LEN + l] /
                     (float)((t == 0) ? cnt0 : cnt1);

    // ========== Phase 1: gather + weighted accumulate -> A hi/mid tiles ==========
    #pragma unroll
    for (int it = 0; it < NPB / 16; it++) {          // 8 nodes per warp
        const int n_local = wid * (NPB / 16) + it;
        const int n = nblk + n_local;
        const bool valid = (n < N_NODES);

        int idx = 0;
        if (valid) {
            idx = paths[(size_t)p * (N_NODES * PATH_LEN)
                        + (size_t)n * PATH_LEN + l];
        }

        float4 a0 = make_float4(0.f, 0.f, 0.f, 0.f);
        float4 a1 = make_float4(0.f, 0.f, 0.f, 0.f);

        if (valid) {
            #pragma unroll
            for (int k = 0; k < 32; k++) {
                const int   id = __shfl_sync(0xffffffffu, idx, k);
                const float w  = __shfl_sync(0xffffffffu, cw,  k);
                const int   tk = __shfl_sync(0xffffffffu, t,   k);
                const float4 v = __ldg(&feats[(size_t)id * (HIDDEN / 4) + lane]);
                if (tk == 0) {
                    a0.x += w * v.x; a0.y += w * v.y;
                    a0.z += w * v.z; a0.w += w * v.w;
                } else {
                    a1.x += w * v.x; a1.y += w * v.y;
                    a1.z += w * v.z; a1.w += w * v.w;
                }
            }
        }
        // row n_local: type0 cols 0..127, type1 cols 128..255 (concat order)
        const uint32_t rb = (uint32_t)n_local * (AP * 2);
        store_split(smem, OFF_AHI, OFF_AMID, rb + 8 * lane,       a0);
        store_split(smem, OFF_AHI, OFF_AMID, rb + 256 + 8 * lane, a1);
    }

    // ========== Phase 2: HMMA GEMM  OUT(128x128) = A(128x256) @ W^T ==========
    // warp w: rows m0..m0+15 (m0 = 16*(w>>1)), cols n0..n0+63 (n0 = 64*(w&1))
    const int m0 = (wid >> 1) * 16;
    const int n0 = (wid & 1) * 64;

    float c[8][4];
    #pragma unroll
    for (int j = 0; j < 8; j++)
        #pragma unroll
        for (int q = 0; q < 4; q++) c[j][q] = 0.f;

    // per-lane ldmatrix base addressing
    const uint32_t a_row = (uint32_t)(m0 + (lane & 15)) * (AP * 2);
    const uint32_t a_kof = (uint32_t)((lane >> 4) * 8) * 2;
    const uint32_t b_row = (uint32_t)(n0 + (lane & 7)) * (WPIT * 2);
    const uint32_t b_kof = (uint32_t)(((lane >> 3) & 1) * 8) * 2;

    #pragma unroll
    for (int kc = 0; kc < FOUT_W / KCHUNK; kc++) {   // 4 chunks
        // ---- stage W chunk [128 rows][64 k] -> hi/mid bf16 ----
        __syncthreads();   // protect previous chunk's readers (and A writes on kc==0)
        #pragma unroll
        for (int i = 0; i < (128 * KCHUNK / 4) / THREADS; i++) {   // 4
            const int e  = tid + i * THREADS;        // 0..2047
            const int j  = e >> 4;                   // W row (output col)
            const int c4 = e & 15;                   // float4 within chunk
            const float4 wv = __ldg((const float4*)(W + (size_t)j * FOUT_W + kc * KCHUNK) + c4);
            store_split(smem, OFF_WHI, OFF_WMID,
                        (uint32_t)j * (WPIT * 2) + (uint32_t)c4 * 8, wv);
        }
        __syncthreads();

        #pragma unroll
        for (int ks = 0; ks < KCHUNK / 16; ks++) {   // 4 k-steps of 16
            const int kg = kc * KCHUNK + ks * 16;    // global k (A)
            const int kl = ks * 16;                  // local k (W chunk)

            uint32_t ah[4], am[4];
            ldm_x4(ah[0], ah[1], ah[2], ah[3], sb + OFF_AHI  + a_row + (uint32_t)kg * 2 + a_kof);
            ldm_x4(am[0], am[1], am[2], am[3], sb + OFF_AMID + a_row + (uint32_t)kg * 2 + a_kof);

            const uint32_t bh_base = sb + OFF_WHI  + b_row + (uint32_t)kl * 2 + b_kof;
            const uint32_t bm_base = sb + OFF_WMID + b_row + (uint32_t)kl * 2 + b_kof;

            #pragma unroll
            for (int j = 0; j < 8; j++) {
                uint32_t bh[2], bm[2];
                ldm_x2(bh[0], bh[1], bh_base + (uint32_t)j * 8 * (WPIT * 2));
                ldm_x2(bm[0], bm[1], bm_base + (uint32_t)j * 8 * (WPIT * 2));
                hmma(c[j], ah, bh);   // hi * hi
                hmma(c[j], ah, bm);   // hi * mid
                hmma(c[j], am, bh);   // mid * hi
            }
        }
    }

    // ========== Epilogue: ReLU + store ==========
    {
        const int r0 = nblk + m0 + (lane >> 2);      // rows r0 and r0+8
        const int cb = n0 + (lane & 3) * 2;
        #pragma unroll
        for (int j = 0; j < 8; j++) {
            const int col = cb + j * 8;
            if (r0 < N_NODES) {
                float2 o0 = make_float2(fmaxf(c[j][0], 0.f), fmaxf(c[j][1], 0.f));
                *(float2*)(out + (size_t)r0 * HIDDEN + col) = o0;
            }
            if (r0 + 8 < N_NODES) {
                float2 o1 = make_float2(fmaxf(c[j][2], 0.f), fmaxf(c[j][3], 0.f));
                *(float2*)(out + (size_t)(r0 + 8) * HIDDEN + col) = o1;
            }
        }
    }
}

extern "C" void kernel_launch(void* const* d_in, const int* in_sizes, int n_in,
                              void* d_out, int out_size)
{
    const float4* feats    = (const float4*)d_in[0];
    const int*    paths    = (const int*)d_in[1];
    const int*    ptypes   = (const int*)d_in[2];
    const float*  pweights = (const float*)d_in[3];
    const float*  W        = (const float*)d_in[4];
    float*        out      = (float*)d_out;

    cudaFuncSetAttribute(impeller_hmma_kernel,
                         cudaFuncAttributeMaxDynamicSharedMemorySize,
                         SMEM_TOTAL);

    const int blocks = (N_NODES + NPB - 1) / NPB;   // 782
    impeller_hmma_kernel<<<blocks, THREADS, SMEM_TOTAL>>>(
        feats, paths, ptypes, pweights, W, out);
}

// round 5
// speedup vs baseline: 1.6401x; 1.1039x over previous
#include <cuda_runtime.h>
#include <cuda_bf16.h>
#include <cstdint>

#define N_NODES  100000
#define HIDDEN   128
#define NUM_PATH 8
#define PATH_LEN 4

#define NPB      64        // nodes per CTA (= GEMM M)
#define THREADS  256       // 8 warps
#define FOUT_W   256       // K of GEMM
#define KCHUNK   64        // W staging chunk along K

#define AP   264           // A pitch (bf16 elems), 528B
#define WPIT 72            // W chunk pitch (bf16 elems), 144B

// smem byte offsets
#define OFF_AHI   0
#define OFF_AMID  (NPB*AP*2)                    // 33792
#define OFF_WHI   (2*NPB*AP*2)                  // 67584
#define OFF_WMID  (OFF_WHI + 128*WPIT*2)        // 86016
#define OFF_WTAB  (OFF_WMID + 128*WPIT*2)       // 104448
#define OFF_TTAB  (OFF_WTAB + 32*4)
#define SMEM_TOTAL (OFF_TTAB + 32*4)            // 104704

__device__ __forceinline__ uint32_t smem_u32(const void* p) {
    uint32_t a;
    asm("{ .reg .u64 t; cvta.to.shared.u64 t, %1; cvt.u32.u64 %0, t; }"
        : "=r"(a) : "l"(p));
    return a;
}
__device__ __forceinline__ void ldm_x4(uint32_t& r0, uint32_t& r1,
                                       uint32_t& r2, uint32_t& r3, uint32_t addr) {
    asm volatile("ldmatrix.sync.aligned.m8n8.x4.shared.b16 {%0,%1,%2,%3}, [%4];"
                 : "=r"(r0), "=r"(r1), "=r"(r2), "=r"(r3) : "r"(addr));
}
__device__ __forceinline__ void hmma(float* c, const uint32_t* a, const uint32_t* b) {
    asm volatile(
        "mma.sync.aligned.m16n8k16.row.col.f32.bf16.bf16.f32 "
        "{%0,%1,%2,%3}, {%4,%5,%6,%7}, {%8,%9}, {%0,%1,%2,%3};"
        : "+f"(c[0]), "+f"(c[1]), "+f"(c[2]), "+f"(c[3])
        : "r"(a[0]), "r"(a[1]), "r"(a[2]), "r"(a[3]), "r"(b[0]), "r"(b[1]));
}

// fp32x4 -> (hi, mid) bf16x4; write 8B to each tile at byte offset `off`
__device__ __forceinline__ void store_split(char* smem, uint32_t hi_base,
                                            uint32_t mid_base, uint32_t off, float4 v) {
    __nv_bfloat16 h0 = __float2bfloat16(v.x);
    __nv_bfloat16 h1 = __float2bfloat16(v.y);
    __nv_bfloat16 h2 = __float2bfloat16(v.z);
    __nv_bfloat16 h3 = __float2bfloat16(v.w);
    __nv_bfloat16 m0 = __float2bfloat16(v.x - __bfloat162float(h0));
    __nv_bfloat16 m1 = __float2bfloat16(v.y - __bfloat162float(h1));
    __nv_bfloat16 m2 = __float2bfloat16(v.z - __bfloat162float(h2));
    __nv_bfloat16 m3 = __float2bfloat16(v.w - __bfloat162float(h3));
    __nv_bfloat162 H01 = __halves2bfloat162(h0, h1);
    __nv_bfloat162 H23 = __halves2bfloat162(h2, h3);
    __nv_bfloat162 M01 = __halves2bfloat162(m0, m1);
    __nv_bfloat162 M23 = __halves2bfloat162(m2, m3);
    *(uint2*)(smem + hi_base + off)  = make_uint2(*(uint32_t*)&H01, *(uint32_t*)&H23);
    *(uint2*)(smem + mid_base + off) = make_uint2(*(uint32_t*)&M01, *(uint32_t*)&M23);
}

__global__ __launch_bounds__(THREADS, 2)
void impeller_hmma_kernel(const float4* __restrict__ feats,
                          const int* __restrict__ paths,
                          const int* __restrict__ ptypes,
                          const float* __restrict__ pweights,
                          const float* __restrict__ W,
                          float* __restrict__ out)
{
    extern __shared__ char smem[];
    const uint32_t sb = smem_u32(smem);
    float* wtab = (float*)(smem + OFF_WTAB);
    int*   ttab = (int*)(smem + OFF_TTAB);

    const int tid  = threadIdx.x;
    const int lane = tid & 31;
    const int wid  = tid >> 5;
    const int nblk = blockIdx.x * NPB;

    // ---- per-pair coefficient table (node-invariant): pair k = (p=k/4, l=k%4)
    if (tid < 32) {
        const int p = tid >> 2;
        const int l = tid & 3;
        const int t = ptypes[p];
        int cnt0 = 0, cnt1 = 0;
        #pragma unroll
        for (int q = 0; q < NUM_PATH; q++) {
            int tq = ptypes[q];
            cnt0 += (tq == 0);
            cnt1 += (tq == 1);
        }
        wtab[tid] = pweights[t * PATH_LEN + l] /
                    (float)((t == 0) ? cnt0 : cnt1);
        ttab[tid] = t;
    }
    __syncthreads();

    // ========== Phase 1: gather + weighted accumulate -> A hi/mid tiles ==========
    #pragma unroll
    for (int it = 0; it < NPB / 8; it++) {           // 8 nodes per warp
        const int n_local = wid * (NPB / 8) + it;
        const int n = nblk + n_local;
        const bool valid = (n < N_NODES);

        int idx = 0;
        if (valid) {
            // lane k owns pair (p=k/4, l=k%4) for this node
            idx = paths[(size_t)(lane >> 2) * (N_NODES * PATH_LEN)
                        + (size_t)n * PATH_LEN + (lane & 3)];
        }

        float4 a0 = make_float4(0.f, 0.f, 0.f, 0.f);
        float4 a1 = make_float4(0.f, 0.f, 0.f, 0.f);

        if (valid) {
            #pragma unroll
            for (int k = 0; k < 32; k++) {
                const int   id = __shfl_sync(0xffffffffu, idx, k);
                const float4 v = __ldg(&feats[(size_t)id * (HIDDEN / 4) + lane]);
                const float w  = wtab[k];     // LDS broadcast, imm offset
                if (ttab[k] == 0) {           // uniform branch
                    a0.x += w * v.x; a0.y += w * v.y;
                    a0.z += w * v.z; a0.w += w * v.w;
                } else {
                    a1.x += w * v.x; a1.y += w * v.y;
                    a1.z += w * v.z; a1.w += w * v.w;
                }
            }
        }
        // row n_local: type0 cols 0..127, type1 cols 128..255 (concat order)
        const uint32_t rb = (uint32_t)n_local * (AP * 2);
        store_split(smem, OFF_AHI, OFF_AMID, rb + 8 * lane,       a0);
        store_split(smem, OFF_AHI, OFF_AMID, rb + 256 + 8 * lane, a1);
    }

    // ========== Phase 2: HMMA GEMM  OUT(64x128) = A(64x256) @ W^T ==========
    // warp w: rows m0..m0+15 (m0=16*(w>>1)), cols n0..n0+63 (n0=64*(w&1))
    const int m0 = (wid >> 1) * 16;
    const int n0 = (wid & 1) * 64;

    float c[8][4];
    #pragma unroll
    for (int j = 0; j < 8; j++)
        #pragma unroll
        for (int q = 0; q < 4; q++) c[j][q] = 0.f;

    // per-lane ldmatrix base addressing
    const uint32_t a_row = (uint32_t)(m0 + (lane & 15)) * (AP * 2);
    const uint32_t a_kof = (uint32_t)((lane >> 4) * 8) * 2;
    // B x4 over j-pairs: lanes 0-15 -> n-block jp*16+0..7, lanes 16-31 -> +8..15
    const uint32_t b_row = (uint32_t)(n0 + ((lane & 16) >> 1) + (lane & 7)) * (WPIT * 2);
    const uint32_t b_kof = (uint32_t)(((lane >> 3) & 1) * 8) * 2;

    #pragma unroll
    for (int kc = 0; kc < FOUT_W / KCHUNK; kc++) {   // 4 chunks
        __syncthreads();   // A ready (kc==0) / previous chunk readers done
        // ---- stage W chunk [128 rows][64 k] -> hi/mid bf16 ----
        #pragma unroll
        for (int i = 0; i < (128 * KCHUNK / 4) / THREADS; i++) {   // 8
            const int e  = tid + i * THREADS;        // 0..2047
            const int j  = e >> 4;                   // W row (output col)
            const int c4 = e & 15;                   // float4 within chunk
            const float4 wv = __ldg((const float4*)(W + (size_t)j * FOUT_W + kc * KCHUNK) + c4);
            store_split(smem, OFF_WHI, OFF_WMID,
                        (uint32_t)j * (WPIT * 2) + (uint32_t)c4 * 8, wv);
        }
        __syncthreads();

        #pragma unroll
        for (int ks = 0; ks < KCHUNK / 16; ks++) {   // 4 k-steps of 16
            const int kg = kc * KCHUNK + ks * 16;    // global k (A)
            const int kl = ks * 16;                  // local k (W chunk)

            uint32_t ah[4], am[4];
            ldm_x4(ah[0], ah[1], ah[2], ah[3], sb + OFF_AHI  + a_row + (uint32_t)kg * 2 + a_kof);
            ldm_x4(am[0], am[1], am[2], am[3], sb + OFF_AMID + a_row + (uint32_t)kg * 2 + a_kof);

            const uint32_t bh_base = sb + OFF_WHI  + b_row + (uint32_t)kl * 2 + b_kof;
            const uint32_t bm_base = sb + OFF_WMID + b_row + (uint32_t)kl * 2 + b_kof;

            #pragma unroll
            for (int jp = 0; jp < 4; jp++) {         // j-pairs
                uint32_t bh[4], bm[4];
                const uint32_t joff = (uint32_t)jp * 16 * (WPIT * 2);
                ldm_x4(bh[0], bh[1], bh[2], bh[3], bh_base + joff);
                ldm_x4(bm[0], bm[1], bm[2], bm[3], bm_base + joff);
                hmma(c[2*jp],   ah, bh);       // hi*hi   (j = 2jp)
                hmma(c[2*jp],   ah, bm);       // hi*mid
                hmma(c[2*jp],   am, bh);       // mid*hi
                hmma(c[2*jp+1], ah, bh + 2);   // j = 2jp+1
                hmma(c[2*jp+1], ah, bm + 2);
                hmma(c[2*jp+1], am, bh + 2);
            }
        }
    }

    // ========== Epilogue: ReLU + store ==========
    {
        const int r0 = nblk + m0 + (lane >> 2);      // rows r0 and r0+8
        const int cb = n0 + (lane & 3) * 2;
        #pragma unroll
        for (int j = 0; j < 8; j++) {
            const int col = cb + j * 8;
            if (r0 < N_NODES) {
                float2 o0 = make_float2(fmaxf(c[j][0], 0.f), fmaxf(c[j][1], 0.f));
                *(float2*)(out + (size_t)r0 * HIDDEN + col) = o0;
            }
            if (r0 + 8 < N_NODES) {
                float2 o1 = make_float2(fmaxf(c[j][2], 0.f), fmaxf(c[j][3], 0.f));
                *(float2*)(out + (size_t)(r0 + 8) * HIDDEN + col) = o1;
            }
        }
    }
}

extern "C" void kernel_launch(void* const* d_in, const int* in_sizes, int n_in,
                              void* d_out, int out_size)
{
    const float4* feats    = (const float4*)d_in[0];
    const int*    paths    = (const int*)d_in[1];
    const int*    ptypes   = (const int*)d_in[2];
    const float*  pweights = (const float*)d_in[3];
    const float*  W        = (const float*)d_in[4];
    float*        out      = (float*)d_out;

    cudaFuncSetAttribute(impeller_hmma_kernel,
                         cudaFuncAttributeMaxDynamicSharedMemorySize,
                         SMEM_TOTAL);

    const int blocks = (N_NODES + NPB - 1) / NPB;   // 1563
    impeller_hmma_kernel<<<blocks, THREADS, SMEM_TOTAL>>>(
        feats, paths, ptypes, pweights, W, out);
}

// round 6
// speedup vs baseline: 1.7643x; 1.0757x over previous
#include <cuda_runtime.h>
#include <cuda_bf16.h>
#include <cstdint>

#define N_NODES  100000
#define HIDDEN   128
#define NUM_PATH 8
#define PATH_LEN 4

#define NPB      64        // nodes per CTA (= GEMM M)
#define THREADS  256       // 8 warps
#define FOUT_W   256       // K of GEMM
#define KCHUNK   64

#define AP   264           // A pitch (bf16 elems), 528B
#define WPIT 72            // prep W chunk pitch (bf16 elems), 144B/row

// main-kernel smem
#define OFF_AHI   0
#define OFF_AMID  (NPB*AP*2)                    // 33792
#define OFF_WTAB  (2*NPB*AP*2)                  // 67584
#define OFF_TTAB  (OFF_WTAB + 32*4)
#define SMEM_TOTAL (OFF_TTAB + 32*4)            // 67840

// precomputed W fragments: [half][kc][ks][nb][lane] -> uint4
//   idx = half*4096 + kc*1024 + ks*256 + nb*32 + lane
__device__ uint4 g_frag[8192];                  // 128 KB
__device__ float g_wtab[32];
__device__ int   g_ttab[32];

__device__ __forceinline__ uint32_t smem_u32(const void* p) {
    uint32_t a;
    asm("{ .reg .u64 t; cvta.to.shared.u64 t, %1; cvt.u32.u64 %0, t; }"
        : "=r"(a) : "l"(p));
    return a;
}
__device__ __forceinline__ void ldm_x4(uint32_t& r0, uint32_t& r1,
                                       uint32_t& r2, uint32_t& r3, uint32_t addr) {
    asm volatile("ldmatrix.sync.aligned.m8n8.x4.shared.b16 {%0,%1,%2,%3}, [%4];"
                 : "=r"(r0), "=r"(r1), "=r"(r2), "=r"(r3) : "r"(addr));
}
__device__ __forceinline__ void hmma(float* c, const uint32_t* a, const uint32_t* b) {
    asm volatile(
        "mma.sync.aligned.m16n8k16.row.col.f32.bf16.bf16.f32 "
        "{%0,%1,%2,%3}, {%4,%5,%6,%7}, {%8,%9}, {%0,%1,%2,%3};"
        : "+f"(c[0]), "+f"(c[1]), "+f"(c[2]), "+f"(c[3])
        : "r"(a[0]), "r"(a[1]), "r"(a[2]), "r"(a[3]), "r"(b[0]), "r"(b[1]));
}

// fp32x4 -> (hi, mid) bf16x4; write 8B to each tile at byte offset `off`
__device__ __forceinline__ void store_split(char* smem, uint32_t hi_base,
                                            uint32_t mid_base, uint32_t off, float4 v) {
    __nv_bfloat16 h0 = __float2bfloat16(v.x);
    __nv_bfloat16 h1 = __float2bfloat16(v.y);
    __nv_bfloat16 h2 = __float2bfloat16(v.z);
    __nv_bfloat16 h3 = __float2bfloat16(v.w);
    __nv_bfloat16 m0 = __float2bfloat16(v.x - __bfloat162float(h0));
    __nv_bfloat16 m1 = __float2bfloat16(v.y - __bfloat162float(h1));
    __nv_bfloat16 m2 = __float2bfloat16(v.z - __bfloat162float(h2));
    __nv_bfloat16 m3 = __float2bfloat16(v.w - __bfloat162float(h3));
    __nv_bfloat162 H01 = __halves2bfloat162(h0, h1);
    __nv_bfloat162 H23 = __halves2bfloat162(h2, h3);
    __nv_bfloat162 M01 = __halves2bfloat162(m0, m1);
    __nv_bfloat162 M23 = __halves2bfloat162(m2, m3);
    *(uint2*)(smem + hi_base + off)  = make_uint2(*(uint32_t*)&H01, *(uint32_t*)&H23);
    *(uint2*)(smem + mid_base + off) = make_uint2(*(uint32_t*)&M01, *(uint32_t*)&M23);
}

// ================= prep kernel: one W chunk per CTA (grid = 4) =================
__global__ __launch_bounds__(256, 1)
void impeller_prep_kernel(const int* __restrict__ ptypes,
                          const float* __restrict__ pweights,
                          const float* __restrict__ W)
{
    __shared__ char psm[2 * 128 * WPIT * 2];     // hi @0, mid @18432
    const int tid  = threadIdx.x;
    const int lane = tid & 31;
    const int wid  = tid >> 5;
    const int kc   = blockIdx.x;                 // 0..3

    if (kc == 0 && tid < 32) {
        const int p = tid >> 2;
        const int l = tid & 3;
        const int t = ptypes[p];
        int cnt0 = 0, cnt1 = 0;
        #pragma unroll
        for (int q = 0; q < NUM_PATH; q++) {
            int tq = ptypes[q];
            cnt0 += (tq == 0);
            cnt1 += (tq == 1);
        }
        g_wtab[tid] = pweights[t * PATH_LEN + l] /
                      (float)((t == 0) ? cnt0 : cnt1);
        g_ttab[tid] = t;
    }

    // convert chunk kc of W (rows j=0..127, k = kc*64 .. +63) into pitched hi/mid
    #pragma unroll
    for (int i = 0; i < 8; i++) {
        const int e  = tid + i * 256;            // 0..2047
        const int j  = e >> 4;
        const int c4 = e & 15;
        const float4 wv = __ldg((const float4*)(W + (size_t)j * FOUT_W + kc * KCHUNK) + c4);
        store_split(psm, 0, 128 * WPIT * 2,
                    (uint32_t)j * (WPIT * 2) + (uint32_t)c4 * 8, wv);
    }
    __syncthreads();

    // extract ldmatrix fragments exactly as the main kernel would
    const uint32_t pb = smem_u32(psm);
    #pragma unroll
    for (int fgi = 0; fgi < 8; fgi++) {
        const int fg   = wid + fgi * 8;          // 0..63
        const int half = fg >> 5;
        const int rem  = fg & 31;
        const int ks   = rem >> 3;
        const int nb   = rem & 7;                // n16-block
        const uint32_t addr = pb + (uint32_t)half * (128 * WPIT * 2)
            + (uint32_t)(nb * 16 + ((lane & 16) >> 1) + (lane & 7)) * (WPIT * 2)
            + (uint32_t)ks * 32 + (uint32_t)(((lane >> 3) & 1) * 16);
        uint32_t r0, r1, r2, r3;
        ldm_x4(r0, r1, r2, r3, addr);
        g_frag[((half * 4 + kc) * 4 + ks) * 8 * 32 + nb * 32 + lane] =
            make_uint4(r0, r1, r2, r3);
    }
}

// ================= main kernel =================
__global__ __launch_bounds__(THREADS, 3)
void impeller_hmma_kernel(const float4* __restrict__ feats,
                          const int* __restrict__ paths,
                          float* __restrict__ out)
{
    extern __shared__ char smem[];
    const uint32_t sb = smem_u32(smem);
    float* wtab = (float*)(smem + OFF_WTAB);
    int*   ttab = (int*)(smem + OFF_TTAB);

    const int tid  = threadIdx.x;
    const int lane = tid & 31;
    const int wid  = tid >> 5;
    const int nblk = blockIdx.x * NPB;

    if (tid < 32) {
        wtab[tid] = g_wtab[tid];
        ttab[tid] = g_ttab[tid];
    }
    __syncthreads();

    // ========== Phase 1: gather + weighted accumulate -> A hi/mid tiles ==========
    #pragma unroll
    for (int it = 0; it < NPB / 8; it++) {           // 8 nodes per warp
        const int n_local = wid * (NPB / 8) + it;
        const int n = nblk + n_local;
        const bool valid = (n < N_NODES);

        int idx = 0;
        if (valid) {
            idx = paths[(size_t)(lane >> 2) * (N_NODES * PATH_LEN)
                        + (size_t)n * PATH_LEN + (lane & 3)];
        }

        float4 a0 = make_float4(0.f, 0.f, 0.f, 0.f);
        float4 a1 = make_float4(0.f, 0.f, 0.f, 0.f);

        if (valid) {
            #pragma unroll
            for (int k = 0; k < 32; k++) {
                const int   id = __shfl_sync(0xffffffffu, idx, k);
                const float4 v = __ldg(&feats[(size_t)id * (HIDDEN / 4) + lane]);
                const float w  = wtab[k];
                if (ttab[k] == 0) {
                    a0.x += w * v.x; a0.y += w * v.y;
                    a0.z += w * v.z; a0.w += w * v.w;
                } else {
                    a1.x += w * v.x; a1.y += w * v.y;
                    a1.z += w * v.z; a1.w += w * v.w;
                }
            }
        }
        const uint32_t rb = (uint32_t)n_local * (AP * 2);
        store_split(smem, OFF_AHI, OFF_AMID, rb + 8 * lane,       a0);
        store_split(smem, OFF_AHI, OFF_AMID, rb + 256 + 8 * lane, a1);
    }
    __syncthreads();

    // ========== Phase 2: HMMA GEMM, B fragments via direct LDG ==========
    const int m0 = (wid >> 1) * 16;
    const int n0 = (wid & 1) * 64;

    float c[8][4];
    #pragma unroll
    for (int j = 0; j < 8; j++)
        #pragma unroll
        for (int q = 0; q < 4; q++) c[j][q] = 0.f;

    const uint32_t a_row = (uint32_t)(m0 + (lane & 15)) * (AP * 2);
    const uint32_t a_kof = (uint32_t)((lane >> 4) * 8) * 2;
    const uint4* fbase = g_frag + (wid & 1) * 128 + lane;   // + kc*1024 + ks*256 + jp*32

    #pragma unroll
    for (int kc = 0; kc < FOUT_W / KCHUNK; kc++) {
        #pragma unroll
        for (int ks = 0; ks < KCHUNK / 16; ks++) {
            const int kg = kc * KCHUNK + ks * 16;

            uint32_t ah[4], am[4];
            ldm_x4(ah[0], ah[1], ah[2], ah[3], sb + OFF_AHI  + a_row + (uint32_t)kg * 2 + a_kof);
            ldm_x4(am[0], am[1], am[2], am[3], sb + OFF_AMID + a_row + (uint32_t)kg * 2 + a_kof);

            const uint4* fk = fbase + kc * 1024 + ks * 256;
            #pragma unroll
            for (int jp = 0; jp < 4; jp++) {
                const uint4 BH = __ldg(fk + jp * 32);          // hi half
                const uint4 BM = __ldg(fk + jp * 32 + 4096);   // mid half
                const uint32_t* bh = (const uint32_t*)&BH;
                const uint32_t* bm = (const uint32_t*)&BM;
                hmma(c[2*jp],   ah, bh);       // hi*hi
                hmma(c[2*jp],   ah, bm);       // hi*mid
                hmma(c[2*jp],   am, bh);       // mid*hi
                hmma(c[2*jp+1], ah, bh + 2);
                hmma(c[2*jp+1], ah, bm + 2);
                hmma(c[2*jp+1], am, bh + 2);
            }
        }
    }

    // ========== Epilogue: ReLU + store ==========
    {
        const int r0 = nblk + m0 + (lane >> 2);
        const int cb = n0 + (lane & 3) * 2;
        #pragma unroll
        for (int j = 0; j < 8; j++) {
            const int col = cb + j * 8;
            if (r0 < N_NODES) {
                float2 o0 = make_float2(fmaxf(c[j][0], 0.f), fmaxf(c[j][1], 0.f));
                *(float2*)(out + (size_t)r0 * HIDDEN + col) = o0;
            }
            if (r0 + 8 < N_NODES) {
                float2 o1 = make_float2(fmaxf(c[j][2], 0.f), fmaxf(c[j][3], 0.f));
                *(float2*)(out + (size_t)(r0 + 8) * HIDDEN + col) = o1;
            }
        }
    }
}

extern "C" void kernel_launch(void* const* d_in, const int* in_sizes, int n_in,
                              void* d_out, int out_size)
{
    const float4* feats    = (const float4*)d_in[0];
    const int*    paths    = (const int*)d_in[1];
    const int*    ptypes   = (const int*)d_in[2];
    const float*  pweights = (const float*)d_in[3];
    const float*  W        = (const float*)d_in[4];
    float*        out      = (float*)d_out;

    impeller_prep_kernel<<<4, 256>>>(ptypes, pweights, W);

    cudaFuncSetAttribute(impeller_hmma_kernel,
                         cudaFuncAttributeMaxDynamicSharedMemorySize,
                         SMEM_TOTAL);
    const int blocks = (N_NODES + NPB - 1) / NPB;   // 1563
    impeller_hmma_kernel<<<blocks, THREADS, SMEM_TOTAL>>>(feats, paths, out);
}

// round 7
// speedup vs baseline: 1.9441x; 1.1019x over previous
#include <cuda_runtime.h>
#include <cuda_bf16.h>
#include <cstdint>

#define N_NODES  100000
#define HIDDEN   128
#define NUM_PATH 8
#define PATH_LEN 4

#define NPB      64        // nodes per CTA (= GEMM M)
#define THREADS  256       // 8 warps
#define FOUT_W   256       // K of GEMM
#define KCHUNK   64

#define AP   264           // A pitch (bf16 elems), 528B
#define AP2  (AP*2)
#define WPIT 72            // prep W chunk pitch (bf16 elems)

// main-kernel smem
#define OFF_AHI   0
#define OFF_AMID  (NPB*AP2)                     // 33792
#define OFF_WTAB  (2*NPB*AP2)                   // 67584
#define SMEM_TOTAL (OFF_WTAB + 32*4)            // 67712

// precomputed W fragments: [half][kc][ks][nb][lane] -> uint4
__device__ uint4 g_frag[8192];                  // 128 KB
__device__ float g_wtab[32];

__device__ __forceinline__ uint32_t smem_u32(const void* p) {
    uint32_t a;
    asm("{ .reg .u64 t; cvta.to.shared.u64 t, %1; cvt.u32.u64 %0, t; }"
        : "=r"(a) : "l"(p));
    return a;
}
__device__ __forceinline__ void ldm_x4(uint32_t& r0, uint32_t& r1,
                                       uint32_t& r2, uint32_t& r3, uint32_t addr) {
    asm volatile("ldmatrix.sync.aligned.m8n8.x4.shared.b16 {%0,%1,%2,%3}, [%4];"
                 : "=r"(r0), "=r"(r1), "=r"(r2), "=r"(r3) : "r"(addr));
}
__device__ __forceinline__ void hmma(float* c, const uint32_t* a, const uint32_t* b) {
    asm volatile(
        "mma.sync.aligned.m16n8k16.row.col.f32.bf16.bf16.f32 "
        "{%0,%1,%2,%3}, {%4,%5,%6,%7}, {%8,%9}, {%0,%1,%2,%3};"
        : "+f"(c[0]), "+f"(c[1]), "+f"(c[2]), "+f"(c[3])
        : "r"(a[0]), "r"(a[1]), "r"(a[2]), "r"(a[3]), "r"(b[0]), "r"(b[1]));
}

// fp32x4 -> (hi, mid) bf16x4; write 8B to each tile at byte offset `off`
__device__ __forceinline__ void store_split(char* smem, uint32_t hi_base,
                                            uint32_t mid_base, uint32_t off, float4 v) {
    __nv_bfloat16 h0 = __float2bfloat16(v.x);
    __nv_bfloat16 h1 = __float2bfloat16(v.y);
    __nv_bfloat16 h2 = __float2bfloat16(v.z);
    __nv_bfloat16 h3 = __float2bfloat16(v.w);
    __nv_bfloat16 m0 = __float2bfloat16(v.x - __bfloat162float(h0));
    __nv_bfloat16 m1 = __float2bfloat16(v.y - __bfloat162float(h1));
    __nv_bfloat16 m2 = __float2bfloat16(v.z - __bfloat162float(h2));
    __nv_bfloat16 m3 = __float2bfloat16(v.w - __bfloat162float(h3));
    __nv_bfloat162 H01 = __halves2bfloat162(h0, h1);
    __nv_bfloat162 H23 = __halves2bfloat162(h2, h3);
    __nv_bfloat162 M01 = __halves2bfloat162(m0, m1);
    __nv_bfloat162 M23 = __halves2bfloat162(m2, m3);
    *(uint2*)(smem + hi_base + off)  = make_uint2(*(uint32_t*)&H01, *(uint32_t*)&H23);
    *(uint2*)(smem + mid_base + off) = make_uint2(*(uint32_t*)&M01, *(uint32_t*)&M23);
}

// ================= prep kernel: one W chunk per CTA (grid = 4) =================
__global__ __launch_bounds__(256, 1)
void impeller_prep_kernel(const int* __restrict__ ptypes,
                          const float* __restrict__ pweights,
                          const float* __restrict__ W)
{
    __shared__ char psm[2 * 128 * WPIT * 2];     // hi @0, mid @18432
    const int tid  = threadIdx.x;
    const int lane = tid & 31;
    const int wid  = tid >> 5;
    const int kc   = blockIdx.x;                 // 0..3

    if (kc == 0 && tid < 32) {
        const int p = tid >> 2;
        const int l = tid & 3;
        const int t = ptypes[p];
        int cnt0 = 0, cnt1 = 0;
        #pragma unroll
        for (int q = 0; q < NUM_PATH; q++) {
            int tq = ptypes[q];
            cnt0 += (tq == 0);
            cnt1 += (tq == 1);
        }
        g_wtab[tid] = pweights[t * PATH_LEN + l] /
                      (float)((t == 0) ? cnt0 : cnt1);
    }

    // convert chunk kc of W (rows j=0..127, k = kc*64 .. +63) into pitched hi/mid
    #pragma unroll
    for (int i = 0; i < 8; i++) {
        const int e  = tid + i * 256;            // 0..2047
        const int j  = e >> 4;
        const int c4 = e & 15;
        const float4 wv = __ldg((const float4*)(W + (size_t)j * FOUT_W + kc * KCHUNK) + c4);
        store_split(psm, 0, 128 * WPIT * 2,
                    (uint32_t)j * (WPIT * 2) + (uint32_t)c4 * 8, wv);
    }
    __syncthreads();

    // extract ldmatrix fragments exactly as the main kernel consumes them
    const uint32_t pb = smem_u32(psm);
    #pragma unroll
    for (int fgi = 0; fgi < 8; fgi++) {
        const int fg   = wid + fgi * 8;          // 0..63
        const int half = fg >> 5;
        const int rem  = fg & 31;
        const int ks   = rem >> 3;
        const int nb   = rem & 7;                // n16-block
        const uint32_t addr = pb + (uint32_t)half * (128 * WPIT * 2)
            + (uint32_t)(nb * 16 + ((lane & 16) >> 1) + (lane & 7)) * (WPIT * 2)
            + (uint32_t)ks * 32 + (uint32_t)(((lane >> 3) & 1) * 16);
        uint32_t r0, r1, r2, r3;
        ldm_x4(r0, r1, r2, r3, addr);
        g_frag[((half * 4 + kc) * 4 + ks) * 8 * 32 + nb * 32 + lane] =
            make_uint4(r0, r1, r2, r3);
    }
}

// ================= main kernel =================
__global__ __launch_bounds__(THREADS, 3)
void impeller_hmma_kernel(const float4* __restrict__ feats,
                          const int* __restrict__ paths,
                          float* __restrict__ out)
{
    extern __shared__ char smem[];
    const uint32_t sb = smem_u32(smem);
    float* wtab = (float*)(smem + OFF_WTAB);

    const int tid  = threadIdx.x;
    const int lane = tid & 31;
    const int wid  = tid >> 5;
    const int nblk = blockIdx.x * NPB;

    if (tid < 32) wtab[tid] = g_wtab[tid];
    __syncthreads();

    // ========== Phase 1: gather + weighted accumulate -> A hi/mid tiles ==========
    // pair k = (p = k/4, l = k%4); edge type is COMPILE-TIME: t = (k>>2)&1
    #pragma unroll
    for (int it = 0; it < NPB / 8; it++) {           // 8 nodes per warp
        const int n_local = wid * (NPB / 8) + it;
        const int n = nblk + n_local;
        const bool valid = (n < N_NODES);

        int idxs = 0;
        if (valid) {
            const int idx = paths[(size_t)(lane >> 2) * (N_NODES * PATH_LEN)
                                  + (size_t)n * PATH_LEN + (lane & 3)];
            idxs = idx << 5;                         // row offset in float4 units
        }

        float4 a0 = make_float4(0.f, 0.f, 0.f, 0.f);
        float4 a1 = make_float4(0.f, 0.f, 0.f, 0.f);

        if (valid) {
            #pragma unroll
            for (int k = 0; k < 32; k++) {
                const int   id = __shfl_sync(0xffffffffu, idxs, k);
                const float4 v = __ldg(&feats[id + lane]);
                const float w  = wtab[k];
                if (((k >> 2) & 1) == 0) {           // compile-time select
                    a0.x += w * v.x; a0.y += w * v.y;
                    a0.z += w * v.z; a0.w += w * v.w;
                } else {
                    a1.x += w * v.x; a1.y += w * v.y;
                    a1.z += w * v.z; a1.w += w * v.w;
                }
            }
        }
        const uint32_t rb = (uint32_t)n_local * AP2;
        store_split(smem, OFF_AHI, OFF_AMID, rb + 8 * lane,       a0);
        store_split(smem, OFF_AHI, OFF_AMID, rb + 256 + 8 * lane, a1);
    }
    __syncthreads();

    // ========== Phase 2: HMMA GEMM, warp tile m32 x n32 ==========
    const int m0 = (wid >> 2) * 32;                  // 2 m-groups
    const int n0 = (wid & 3) * 32;                   // 4 n-groups
    const int nb0 = (wid & 3) * 2;                   // first n16 frag block

    float c[2][4][4];
    #pragma unroll
    for (int mt = 0; mt < 2; mt++)
        #pragma unroll
        for (int j = 0; j < 4; j++)
            #pragma unroll
            for (int q = 0; q < 4; q++) c[mt][j][q] = 0.f;

    const uint32_t a_row0 = (uint32_t)(m0 + (lane & 15)) * AP2;
    const uint32_t a_row1 = a_row0 + 16 * AP2;
    const uint32_t a_kof  = (uint32_t)((lane >> 4) * 16);
    const uint4* fbase = g_frag + nb0 * 32 + lane;   // + kc*1024 + ks*256 (+4096 mid)

    #pragma unroll
    for (int kc = 0; kc < FOUT_W / KCHUNK; kc++) {
        #pragma unroll
        for (int ks = 0; ks < KCHUNK / 16; ks++) {
            const uint32_t kgb = (uint32_t)(kc * KCHUNK + ks * 16) * 2;

            uint32_t ah0[4], am0[4], ah1[4], am1[4];
            ldm_x4(ah0[0], ah0[1], ah0[2], ah0[3], sb + OFF_AHI  + a_row0 + kgb + a_kof);
            ldm_x4(am0[0], am0[1], am0[2], am0[3], sb + OFF_AMID + a_row0 + kgb + a_kof);
            ldm_x4(ah1[0], ah1[1], ah1[2], ah1[3], sb + OFF_AHI  + a_row1 + kgb + a_kof);
            ldm_x4(am1[0], am1[1], am1[2], am1[3], sb + OFF_AMID + a_row1 + kgb + a_kof);

            const uint4* fk = fbase + kc * 1024 + ks * 256;
            #pragma unroll
            for (int jl = 0; jl < 2; jl++) {         // 2 local n16 blocks
                const uint4 BH = __ldg(fk + jl * 32);
                const uint4 BM = __ldg(fk + jl * 32 + 4096);
                const uint32_t* bh = (const uint32_t*)&BH;
                const uint32_t* bm = (const uint32_t*)&BM;
                hmma(c[0][2*jl],   ah0, bh);
                hmma(c[0][2*jl],   ah0, bm);
                hmma(c[0][2*jl],   am0, bh);
                hmma(c[0][2*jl+1], ah0, bh + 2);
                hmma(c[0][2*jl+1], ah0, bm + 2);
                hmma(c[0][2*jl+1], am0, bh + 2);
                hmma(c[1][2*jl],   ah1, bh);
                hmma(c[1][2*jl],   ah1, bm);
                hmma(c[1][2*jl],   am1, bh);
                hmma(c[1][2*jl+1], ah1, bh + 2);
                hmma(c[1][2*jl+1], ah1, bm + 2);
                hmma(c[1][2*jl+1], am1, bh + 2);
            }
        }
    }

    // ========== Epilogue: ReLU + store ==========
    #pragma unroll
    for (int mt = 0; mt < 2; mt++) {
        const int r0 = nblk + m0 + mt * 16 + (lane >> 2);
        #pragma unroll
        for (int j = 0; j < 4; j++) {
            const int col = n0 + j * 8 + (lane & 3) * 2;
            if (r0 < N_NODES) {
                float2 o0 = make_float2(fmaxf(c[mt][j][0], 0.f), fmaxf(c[mt][j][1], 0.f));
                *(float2*)(out + (size_t)r0 * HIDDEN + col) = o0;
            }
            if (r0 + 8 < N_NODES) {
                float2 o1 = make_float2(fmaxf(c[mt][j][2], 0.f), fmaxf(c[mt][j][3], 0.f));
                *(float2*)(out + (size_t)(r0 + 8) * HIDDEN + col) = o1;
            }
        }
    }
}

extern "C" void kernel_launch(void* const* d_in, const int* in_sizes, int n_in,
                              void* d_out, int out_size)
{
    const float4* feats    = (const float4*)d_in[0];
    const int*    paths    = (const int*)d_in[1];
    const int*    ptypes   = (const int*)d_in[2];
    const float*  pweights = (const float*)d_in[3];
    const float*  W        = (const float*)d_in[4];
    float*        out      = (float*)d_out;

    impeller_prep_kernel<<<4, 256>>>(ptypes, pweights, W);

    cudaFuncSetAttribute(impeller_hmma_kernel,
                         cudaFuncAttributeMaxDynamicSharedMemorySize,
                         SMEM_TOTAL);
    const int blocks = (N_NODES + NPB - 1) / NPB;   // 1563
    impeller_hmma_kernel<<<blocks, THREADS, SMEM_TOTAL>>>(feats, paths, out);
}